// round 6
// baseline (speedup 1.0000x reference)
#include <cuda_runtime.h>
#include <cuda_bf16.h>
#include <cstdint>

#define B_   256
#define P_   4
#define D_   768
#define U_   32
#define IN_  3072

#define BM 128
#define BN 128
#define BK 32
#define NTILES (IN_ / BK)   // 96
#define THREADS 256

// smem: rows are 136 bf16 = 272B (conflict-free trans ldmatrix, proven R3/R5)
#define ROW_B    272
#define PLANE_SZ (32 * ROW_B)        // 8704
#define AST_SZ   (2 * PLANE_SZ)      // 17408 per A stage (hi+lo)
#define BST_SZ   (2 * PLANE_SZ)      // per B stage
#define A_STAGES 3
#define B_STAGES 2
#define OFF_B    (A_STAGES * AST_SZ) // 52224
#define SMEM_TOTAL (A_STAGES * AST_SZ + B_STAGES * BST_SZ)  // 87040

// Pre-converted A, K-major: [IN_][B_] bf16 hi/lo planes
__device__ __align__(16) __nv_bfloat16 g_Ahi[IN_ * B_];
__device__ __align__(16) __nv_bfloat16 g_Alo[IN_ * B_];

__device__ __forceinline__ uint32_t smem_u32(const void* p) {
    uint32_t a;
    asm("{ .reg .u64 t; cvta.to.shared.u64 t, %1; cvt.u32.u64 %0, t; }" : "=r"(a) : "l"(p));
    return a;
}
#define CP_ASYNC16(dst, src) \
    asm volatile("cp.async.cg.shared.global [%0], [%1], 16;" :: "r"(dst), "l"(src))
#define CP_COMMIT() asm volatile("cp.async.commit_group;" ::: "memory")
#define CP_WAIT1()  asm volatile("cp.async.wait_group 1;" ::: "memory")

#define LDSM_X4T(r, addr) \
    asm volatile("ldmatrix.sync.aligned.m8n8.x4.trans.shared.b16 {%0,%1,%2,%3}, [%4];" \
        : "=r"((r)[0]), "=r"((r)[1]), "=r"((r)[2]), "=r"((r)[3]) : "r"(addr))
#define MMA16816(d, a, b0, b1) \
    asm volatile("mma.sync.aligned.m16n8k16.row.col.f32.bf16.bf16.f32 " \
        "{%0,%1,%2,%3}, {%4,%5,%6,%7}, {%8,%9}, {%0,%1,%2,%3};" \
        : "+f"((d)[0]), "+f"((d)[1]), "+f"((d)[2]), "+f"((d)[3]) \
        : "r"((a)[0]), "r"((a)[1]), "r"((a)[2]), "r"((a)[3]), "r"(b0), "r"(b1))

// hi = [bf16(y) : bf16(x)], lo = [bf16(y-hy) : bf16(x-hx)] — 6 instrs / 2 values
__device__ __forceinline__ void cvt_hilo2(float x, float y, uint32_t& hi, uint32_t& lo) {
    asm("cvt.rn.bf16x2.f32 %0, %1, %2;" : "=r"(hi) : "f"(y), "f"(x));
    float xh = __uint_as_float(hi << 16);
    float yh = __uint_as_float(hi & 0xffff0000u);
    float dx = x - xh;
    float dy = y - yh;
    asm("cvt.rn.bf16x2.f32 %0, %1, %2;" : "=r"(lo) : "f"(dy), "f"(dx));
}

// ---------------- Fused pre-pass: A -> K-major bf16 hi/lo planes + mean ----------------
// grid (B_/32, D_/32) = (8, 24), 256 threads
__global__ void coldprompt_prep_mean(const float* __restrict__ A, float* __restrict__ mean_out)
{
    __shared__ float T[32][33];
    const int tid = threadIdx.x;
    const int b0  = blockIdx.x * 32;
    const int d0  = blockIdx.y * 32;

    const int bb  = tid >> 3;
    const int dd4 = (tid & 7) * 4;
    const int kk  = tid >> 3;
    const int bb4 = (tid & 7) * 4;

    float4 s = make_float4(0.f, 0.f, 0.f, 0.f);

    #pragma unroll
    for (int p = 0; p < P_; ++p) {
        float4 v = *(const float4*)(A + ((size_t)(b0 + bb) * P_ + p) * D_ + d0 + dd4);
        s.x += v.x; s.y += v.y; s.z += v.z; s.w += v.w;
        T[dd4 + 0][bb] = v.x;
        T[dd4 + 1][bb] = v.y;
        T[dd4 + 2][bb] = v.z;
        T[dd4 + 3][bb] = v.w;
        __syncthreads();
        {
            float x0 = T[kk][bb4 + 0], x1 = T[kk][bb4 + 1];
            float x2 = T[kk][bb4 + 2], x3 = T[kk][bb4 + 3];
            uint32_t h0, l0, h1, l1;
            cvt_hilo2(x0, x1, h0, l0);
            cvt_hilo2(x2, x3, h1, l1);
            const size_t o = (size_t)(p * D_ + d0 + kk) * B_ + b0 + bb4;
            *(uint2*)(g_Ahi + o) = make_uint2(h0, h1);
            *(uint2*)(g_Alo + o) = make_uint2(l0, l1);
        }
        __syncthreads();
    }
    s.x *= 0.25f; s.y *= 0.25f; s.z *= 0.25f; s.w *= 0.25f;
    *(float4*)(mean_out + (size_t)(b0 + bb) * D_ + d0 + dd4) = s;
}

// ---------------- Main GEMM ----------------
__global__ void __launch_bounds__(THREADS, 1)
coldprompt_mma_gemm(const float* __restrict__ W,     // [32, 3072, 768]
                    const float* __restrict__ bias,  // [32, 768]
                    float* __restrict__ C)           // [32*256, 768]
{
    extern __shared__ char smem[];
    const uint32_t sb = smem_u32(smem);

    const int tid  = threadIdx.x;
    const int wid  = tid >> 5;
    const int lane = tid & 31;
    const int u    = blockIdx.z;
    const int m0   = blockIdx.y * BM;
    const int n0   = blockIdx.x * BN;

    const int wm = (wid >> 2) * 64;   // 2 m-warps of 64
    const int wn = (wid & 3) * 32;    // 4 n-warps of 32

    const float* __restrict__ Wbase = W + (size_t)u * IN_ * D_ + n0;

    // A cp.async mapping: 2 chunks of 16B per plane per thread
    const int a_kr0 = tid >> 4;           // k-row 0..15 (chunk 0), +16 (chunk 1)
    const int a_m8  = (tid & 15) * 8;     // m elem offset (16B)
    // B LDG mapping: 4 chunks of float4
    const int b_kr0 = tid >> 5;           // 0..7 (+8c)
    const int b_n4  = (tid & 31) * 4;

    float acc[4][4][4];
    #pragma unroll
    for (int i = 0; i < 4; i++)
        #pragma unroll
        for (int j = 0; j < 4; j++) {
            acc[i][j][0] = 0.f; acc[i][j][1] = 0.f;
            acc[i][j][2] = 0.f; acc[i][j][3] = 0.f;
        }

    float4 breg[2][4];   // depth-2 B prefetch

    auto ISSUE_A = [&](int it) {
        const uint32_t st = sb + (it % A_STAGES) * AST_SZ;
        const size_t gk = (size_t)it * BK * B_ + m0;
        #pragma unroll
        for (int c = 0; c < 2; ++c) {
            const int kr = a_kr0 + c * 16;
            const uint32_t doff = kr * ROW_B + a_m8 * 2;
            CP_ASYNC16(st + doff,            g_Ahi + gk + (size_t)kr * B_ + a_m8);
            CP_ASYNC16(st + PLANE_SZ + doff, g_Alo + gk + (size_t)kr * B_ + a_m8);
        }
    };
    auto LDG_B = [&](int it, float4 (&r)[4]) {
        const int k0 = it * BK;
        #pragma unroll
        for (int c = 0; c < 4; ++c)
            r[c] = *(const float4*)(Wbase + (size_t)(k0 + b_kr0 + c * 8) * D_ + b_n4);
    };
    auto STS_B = [&](int it, const float4 (&v)[4]) {
        char* st = smem + OFF_B + (it & 1) * BST_SZ;
        #pragma unroll
        for (int c = 0; c < 4; ++c) {
            uint32_t h0, l0, h1, l1;
            cvt_hilo2(v[c].x, v[c].y, h0, l0);
            cvt_hilo2(v[c].z, v[c].w, h1, l1);
            char* p = st + (b_kr0 + c * 8) * ROW_B + b_n4 * 2;
            *(uint2*)p              = make_uint2(h0, h1);
            *(uint2*)(p + PLANE_SZ) = make_uint2(l0, l1);
        }
    };

    // ldmatrix lane address components
    const uint32_t a_krow = (lane & 7) + ((lane >> 4) & 1) * 8;
    const uint32_t a_mcol = ((lane >> 3) & 1) * 8;
    const uint32_t b_krow = (lane & 7) + ((lane >> 3) & 1) * 8;
    const uint32_t b_ncol = (lane >> 4) * 8;

    auto COMPUTE = [&](int it) {
        const uint32_t sa = sb + (it % A_STAGES) * AST_SZ;
        const uint32_t sB = sb + OFF_B + (it & 1) * BST_SZ;
        #pragma unroll
        for (int ks = 0; ks < 2; ++ks) {
            uint32_t a_hi[4][4], a_lo[4][4];
            #pragma unroll
            for (int mt = 0; mt < 4; ++mt) {
                const uint32_t ao =
                    (ks * 16 + a_krow) * ROW_B + (wm + mt * 16 + a_mcol) * 2;
                LDSM_X4T(a_hi[mt], sa + ao);
                LDSM_X4T(a_lo[mt], sa + PLANE_SZ + ao);
            }
            uint32_t b_hi[8], b_lo[8];
            #pragma unroll
            for (int nt2 = 0; nt2 < 2; ++nt2) {
                const uint32_t bo =
                    (ks * 16 + b_krow) * ROW_B + (wn + nt2 * 16 + b_ncol) * 2;
                LDSM_X4T(&b_hi[nt2 * 4], sB + bo);
                LDSM_X4T(&b_lo[nt2 * 4], sB + PLANE_SZ + bo);
            }
            #pragma unroll
            for (int mt = 0; mt < 4; ++mt)
                #pragma unroll
                for (int nt = 0; nt < 4; ++nt) {
                    MMA16816(acc[mt][nt], a_hi[mt], b_hi[nt * 2], b_hi[nt * 2 + 1]);
                    MMA16816(acc[mt][nt], a_hi[mt], b_lo[nt * 2], b_lo[nt * 2 + 1]);
                    MMA16816(acc[mt][nt], a_lo[mt], b_hi[nt * 2], b_hi[nt * 2 + 1]);
                }
        }
    };

    // ---- prologue ----
    LDG_B(0, breg[0]);
    LDG_B(1, breg[1]);
    ISSUE_A(0); CP_COMMIT();
    ISSUE_A(1); CP_COMMIT();
    STS_B(0, breg[0]);

    // ---- mainloop: ONE sync per tile ----
    #pragma unroll 1
    for (int it = 0; it < NTILES; ++it) {
        CP_WAIT1();            // A(it) landed (A(it+1) may be in flight)
        __syncthreads();       // A(it) + B(it) visible; all warps past COMPUTE(it-1)
        if (it + 2 < NTILES) {
            LDG_B(it + 2, breg[it & 1]);   // breg[it&1] content (tile it) was stored last iter
            ISSUE_A(it + 2);
        }
        CP_COMMIT();           // uniform group count
        if (it + 1 < NTILES) STS_B(it + 1, breg[(it + 1) & 1]);
        COMPUTE(it);
    }

    // ---- epilogue ----
    const int g  = lane >> 2;
    const int tq = lane & 3;
    #pragma unroll
    for (int mt = 0; mt < 4; ++mt) {
        #pragma unroll
        for (int nt = 0; nt < 4; ++nt) {
            const int row0 = m0 + wm + mt * 16 + g;
            const int col  = n0 + wn + nt * 8 + tq * 2;
            const float2 bv = *(const float2*)(bias + (size_t)u * D_ + col);
            float* c0 = C + ((size_t)u * B_ + row0) * D_ + col;
            float* c1 = c0 + (size_t)8 * D_;
            float2 o0, o1;
            o0.x = acc[mt][nt][0] + bv.x;
            o0.y = acc[mt][nt][1] + bv.y;
            o1.x = acc[mt][nt][2] + bv.x;
            o1.y = acc[mt][nt][3] + bv.y;
            *(float2*)c0 = o0;
            *(float2*)c1 = o1;
        }
    }
}

extern "C" void kernel_launch(void* const* d_in, const int* in_sizes, int n_in,
                              void* d_out, int out_size)
{
    const float* weight = (const float*)d_in[0];
    const float* W_spec = (const float*)d_in[1];
    const float* b_spec = (const float*)d_in[2];
    float* out = (float*)d_out;

    cudaFuncSetAttribute(coldprompt_mma_gemm,
                         cudaFuncAttributeMaxDynamicSharedMemorySize, SMEM_TOTAL);

    // 2 launches per call -> odd ncu skip indices land on the GEMM
    dim3 pgrid(B_ / 32, D_ / 32);   // (8, 24)
    coldprompt_prep_mean<<<pgrid, 256>>>(weight, out + (size_t)U_ * B_ * D_);

    dim3 grid(D_ / BN, B_ / BM, U_);   // (6, 2, 32)
    coldprompt_mma_gemm<<<grid, THREADS, SMEM_TOTAL>>>(W_spec, b_spec, out);
}

// round 7
// speedup vs baseline: 1.0089x; 1.0089x over previous
#include <cuda_runtime.h>
#include <cuda_bf16.h>
#include <cstdint>

#define B_   256
#define P_   4
#define D_   768
#define U_   32
#define IN_  3072

#define BM 128
#define BN 128
#define BK 32
#define NTILES (IN_ / BK)   // 96
#define THREADS 512

// smem: rows are 136 bf16 = 272B (conflict-free trans ldmatrix, proven)
#define ROW_B    272
#define PLANE_SZ (32 * ROW_B)        // 8704
#define AST_SZ   (2 * PLANE_SZ)      // 17408 per A stage (hi+lo)
#define BST_SZ   (2 * PLANE_SZ)
#define A_STAGES 3
#define B_STAGES 2
#define OFF_B    (A_STAGES * AST_SZ) // 52224
#define SMEM_TOTAL (A_STAGES * AST_SZ + B_STAGES * BST_SZ)  // 87040

// Pre-converted A, K-major: [IN_][B_] bf16 hi/lo planes
__device__ __align__(16) __nv_bfloat16 g_Ahi[IN_ * B_];
__device__ __align__(16) __nv_bfloat16 g_Alo[IN_ * B_];

__device__ __forceinline__ uint32_t smem_u32(const void* p) {
    uint32_t a;
    asm("{ .reg .u64 t; cvta.to.shared.u64 t, %1; cvt.u32.u64 %0, t; }" : "=r"(a) : "l"(p));
    return a;
}
#define CP_ASYNC16(dst, src) \
    asm volatile("cp.async.cg.shared.global [%0], [%1], 16;" :: "r"(dst), "l"(src))
#define CP_COMMIT() asm volatile("cp.async.commit_group;" ::: "memory")
#define CP_WAIT1()  asm volatile("cp.async.wait_group 1;" ::: "memory")

#define LDSM_X4T(r, addr) \
    asm volatile("ldmatrix.sync.aligned.m8n8.x4.trans.shared.b16 {%0,%1,%2,%3}, [%4];" \
        : "=r"((r)[0]), "=r"((r)[1]), "=r"((r)[2]), "=r"((r)[3]) : "r"(addr))
#define MMA16816(d, a, b0, b1) \
    asm volatile("mma.sync.aligned.m16n8k16.row.col.f32.bf16.bf16.f32 " \
        "{%0,%1,%2,%3}, {%4,%5,%6,%7}, {%8,%9}, {%0,%1,%2,%3};" \
        : "+f"((d)[0]), "+f"((d)[1]), "+f"((d)[2]), "+f"((d)[3]) \
        : "r"((a)[0]), "r"((a)[1]), "r"((a)[2]), "r"((a)[3]), "r"(b0), "r"(b1))

// hi = [bf16(y) : bf16(x)], lo = residual pair — 6 instrs / 2 values
__device__ __forceinline__ void cvt_hilo2(float x, float y, uint32_t& hi, uint32_t& lo) {
    asm("cvt.rn.bf16x2.f32 %0, %1, %2;" : "=r"(hi) : "f"(y), "f"(x));
    float xh = __uint_as_float(hi << 16);
    float yh = __uint_as_float(hi & 0xffff0000u);
    float dx = x - xh;
    float dy = y - yh;
    asm("cvt.rn.bf16x2.f32 %0, %1, %2;" : "=r"(lo) : "f"(dy), "f"(dx));
}

// ---------------- Fused pre-pass: A -> K-major bf16 hi/lo planes + mean ----------------
__global__ void coldprompt_prep_mean(const float* __restrict__ A, float* __restrict__ mean_out)
{
    __shared__ float T[32][33];
    const int tid = threadIdx.x;
    const int b0  = blockIdx.x * 32;
    const int d0  = blockIdx.y * 32;

    const int bb  = tid >> 3;
    const int dd4 = (tid & 7) * 4;
    const int kk  = tid >> 3;
    const int bb4 = (tid & 7) * 4;

    float4 s = make_float4(0.f, 0.f, 0.f, 0.f);

    #pragma unroll
    for (int p = 0; p < P_; ++p) {
        float4 v = *(const float4*)(A + ((size_t)(b0 + bb) * P_ + p) * D_ + d0 + dd4);
        s.x += v.x; s.y += v.y; s.z += v.z; s.w += v.w;
        T[dd4 + 0][bb] = v.x;
        T[dd4 + 1][bb] = v.y;
        T[dd4 + 2][bb] = v.z;
        T[dd4 + 3][bb] = v.w;
        __syncthreads();
        {
            float x0 = T[kk][bb4 + 0], x1 = T[kk][bb4 + 1];
            float x2 = T[kk][bb4 + 2], x3 = T[kk][bb4 + 3];
            uint32_t h0, l0, h1, l1;
            cvt_hilo2(x0, x1, h0, l0);
            cvt_hilo2(x2, x3, h1, l1);
            const size_t o = (size_t)(p * D_ + d0 + kk) * B_ + b0 + bb4;
            *(uint2*)(g_Ahi + o) = make_uint2(h0, h1);
            *(uint2*)(g_Alo + o) = make_uint2(l0, l1);
        }
        __syncthreads();
    }
    s.x *= 0.25f; s.y *= 0.25f; s.z *= 0.25f; s.w *= 0.25f;
    *(float4*)(mean_out + (size_t)(b0 + bb) * D_ + d0 + dd4) = s;
}

// ---------------- Main GEMM: 512 threads, 16 warps, warp tile 32x32 ----------------
__global__ void __launch_bounds__(THREADS, 1)
coldprompt_mma_gemm(const float* __restrict__ W,     // [32, 3072, 768]
                    const float* __restrict__ bias,  // [32, 768]
                    float* __restrict__ C)           // [32*256, 768]
{
    extern __shared__ char smem[];
    const uint32_t sb = smem_u32(smem);

    const int tid  = threadIdx.x;
    const int wid  = tid >> 5;
    const int lane = tid & 31;
    const int u    = blockIdx.z;
    const int m0   = blockIdx.y * BM;
    const int n0   = blockIdx.x * BN;

    const int wm = (wid & 3) * 32;    // 4 m-warps of 32
    const int wn = (wid >> 2) * 32;   // 4 n-warps of 32

    const float* __restrict__ Wbase = W + (size_t)u * IN_ * D_ + n0;

    // A cp.async mapping: 1 chunk of 16B per plane per thread (512 thr cover 32x128)
    const int a_kr = tid >> 4;            // k-row 0..31
    const int a_m8 = (tid & 15) * 8;      // m elem offset (16B)
    // B LDG mapping: 2 float4 per thread
    const int b_kr0 = tid >> 5;           // 0..15 (+16 for c=1)
    const int b_n4  = (tid & 31) * 4;

    float acc[2][4][4];
    #pragma unroll
    for (int i = 0; i < 2; i++)
        #pragma unroll
        for (int j = 0; j < 4; j++) {
            acc[i][j][0] = 0.f; acc[i][j][1] = 0.f;
            acc[i][j][2] = 0.f; acc[i][j][3] = 0.f;
        }

    float4 breg[2][2];   // depth-2 B prefetch, 2 float4 each

    auto ISSUE_A = [&](int it) {
        const uint32_t st = sb + (it % A_STAGES) * AST_SZ;
        const size_t gk = (size_t)it * BK * B_ + m0 + (size_t)a_kr * B_ + a_m8;
        const uint32_t doff = a_kr * ROW_B + a_m8 * 2;
        CP_ASYNC16(st + doff,            g_Ahi + gk);
        CP_ASYNC16(st + PLANE_SZ + doff, g_Alo + gk);
    };
    auto LDG_B = [&](int it, float4 (&r)[2]) {
        const int k0 = it * BK;
        #pragma unroll
        for (int c = 0; c < 2; ++c)
            r[c] = *(const float4*)(Wbase + (size_t)(k0 + b_kr0 + c * 16) * D_ + b_n4);
    };
    auto STS_B = [&](int it, const float4 (&v)[2]) {
        char* st = smem + OFF_B + (it & 1) * BST_SZ;
        #pragma unroll
        for (int c = 0; c < 2; ++c) {
            uint32_t h0, l0, h1, l1;
            cvt_hilo2(v[c].x, v[c].y, h0, l0);
            cvt_hilo2(v[c].z, v[c].w, h1, l1);
            char* p = st + (b_kr0 + c * 16) * ROW_B + b_n4 * 2;
            *(uint2*)p              = make_uint2(h0, h1);
            *(uint2*)(p + PLANE_SZ) = make_uint2(l0, l1);
        }
    };

    // ldmatrix lane address components (proven mapping)
    const uint32_t a_krow = (lane & 7) + ((lane >> 4) & 1) * 8;
    const uint32_t a_mcol = ((lane >> 3) & 1) * 8;
    const uint32_t b_krow = (lane & 7) + ((lane >> 3) & 1) * 8;
    const uint32_t b_ncol = (lane >> 4) * 8;

    auto COMPUTE = [&](int it) {
        const uint32_t sa = sb + (it % A_STAGES) * AST_SZ;
        const uint32_t sB = sb + OFF_B + (it & 1) * BST_SZ;
        #pragma unroll
        for (int ks = 0; ks < 2; ++ks) {
            uint32_t a_hi[2][4], a_lo[2][4];
            #pragma unroll
            for (int mt = 0; mt < 2; ++mt) {
                const uint32_t ao =
                    (ks * 16 + a_krow) * ROW_B + (wm + mt * 16 + a_mcol) * 2;
                LDSM_X4T(a_hi[mt], sa + ao);
                LDSM_X4T(a_lo[mt], sa + PLANE_SZ + ao);
            }
            uint32_t b_hi[8], b_lo[8];
            #pragma unroll
            for (int nt2 = 0; nt2 < 2; ++nt2) {
                const uint32_t bo =
                    (ks * 16 + b_krow) * ROW_B + (wn + nt2 * 16 + b_ncol) * 2;
                LDSM_X4T(&b_hi[nt2 * 4], sB + bo);
                LDSM_X4T(&b_lo[nt2 * 4], sB + PLANE_SZ + bo);
            }
            #pragma unroll
            for (int mt = 0; mt < 2; ++mt)
                #pragma unroll
                for (int nt = 0; nt < 4; ++nt) {
                    MMA16816(acc[mt][nt], a_hi[mt], b_hi[nt * 2], b_hi[nt * 2 + 1]);
                    MMA16816(acc[mt][nt], a_hi[mt], b_lo[nt * 2], b_lo[nt * 2 + 1]);
                    MMA16816(acc[mt][nt], a_lo[mt], b_hi[nt * 2], b_hi[nt * 2 + 1]);
                }
        }
    };

    // ---- prologue ----
    LDG_B(0, breg[0]);
    LDG_B(1, breg[1]);
    ISSUE_A(0); CP_COMMIT();
    ISSUE_A(1); CP_COMMIT();
    STS_B(0, breg[0]);

    // ---- mainloop: one sync per tile ----
    #pragma unroll 1
    for (int it = 0; it < NTILES; ++it) {
        CP_WAIT1();            // A(it) landed
        __syncthreads();       // A(it)+B(it) visible; all warps past COMPUTE(it-1)
        if (it + 2 < NTILES) {
            LDG_B(it + 2, breg[it & 1]);
            ISSUE_A(it + 2);
        }
        CP_COMMIT();
        if (it + 1 < NTILES) STS_B(it + 1, breg[(it + 1) & 1]);
        COMPUTE(it);
    }

    // ---- epilogue ----
    const int g  = lane >> 2;
    const int tq = lane & 3;
    #pragma unroll
    for (int mt = 0; mt < 2; ++mt) {
        #pragma unroll
        for (int nt = 0; nt < 4; ++nt) {
            const int row0 = m0 + wm + mt * 16 + g;
            const int col  = n0 + wn + nt * 8 + tq * 2;
            const float2 bv = *(const float2*)(bias + (size_t)u * D_ + col);
            float* c0 = C + ((size_t)u * B_ + row0) * D_ + col;
            float* c1 = c0 + (size_t)8 * D_;
            float2 o0, o1;
            o0.x = acc[mt][nt][0] + bv.x;
            o0.y = acc[mt][nt][1] + bv.y;
            o1.x = acc[mt][nt][2] + bv.x;
            o1.y = acc[mt][nt][3] + bv.y;
            *(float2*)c0 = o0;
            *(float2*)c1 = o1;
        }
    }
}

extern "C" void kernel_launch(void* const* d_in, const int* in_sizes, int n_in,
                              void* d_out, int out_size)
{
    const float* weight = (const float*)d_in[0];
    const float* W_spec = (const float*)d_in[1];
    const float* b_spec = (const float*)d_in[2];
    float* out = (float*)d_out;

    cudaFuncSetAttribute(coldprompt_mma_gemm,
                         cudaFuncAttributeMaxDynamicSharedMemorySize, SMEM_TOTAL);

    dim3 pgrid(B_ / 32, D_ / 32);   // (8, 24)
    coldprompt_prep_mean<<<pgrid, 256>>>(weight, out + (size_t)U_ * B_ * D_);

    dim3 grid(D_ / BN, B_ / BM, U_);   // (6, 2, 32)
    coldprompt_mma_gemm<<<grid, THREADS, SMEM_TOTAL>>>(W_spec, b_spec, out);
}